// round 6
// baseline (speedup 1.0000x reference)
#include <cuda_runtime.h>

// ActiveParticles step, N=4096.
// Inputs: positions[N,2] f32, orientations[N,2] f32, Deltas[1] f32,
//         rot_noise[N] f32, trans_noise[N,2] f32.
// Output: [5, N, 2] f32 = {new_p, new_u, orientation_sums, leftturns, rightturns}.

#define NMAX 4096

static __device__ float2 g_cms;
static __device__ float4 g_pu[NMAX];          // (p.x, p.y, u.x, u.y)
static __device__ float4 g_posA4[NMAX / 2];   // positions ping (float2 pairs)
static __device__ float4 g_posB4[NMAX / 2];   // positions pong

__device__ __forceinline__ float wsum(float v) {
#pragma unroll
    for (int o = 16; o; o >>= 1) v += __shfl_xor_sync(0xffffffffu, v, o);
    return v;
}

__device__ __forceinline__ float anglewrap(float diff) {
    const float PI_F = 3.1415927410125732f;
    if (diff <= -PI_F) diff = diff - PI_F * floorf(diff / PI_F);  // jnp.mod(diff, PI)
    if (diff >= PI_F) diff -= 2.0f * PI_F;
    return diff;
}

__device__ __forceinline__ float anglediff(float ax, float ay, float bx, float by) {
    return anglewrap(atan2f(ay, ax) - atan2f(by, bx));
}

// ------------- prep: pack (p,u) -> g_pu; block 0 computes mean(p) -----------------
__global__ void prep_kernel(const float2* __restrict__ p, const float2* __restrict__ u, int n) {
    int i = blockIdx.x * blockDim.x + threadIdx.x;
    if (i < n) {
        float2 pp = p[i], uu = u[i];
        g_pu[i] = make_float4(pp.x, pp.y, uu.x, uu.y);
    }
    if (blockIdx.x == 0) {
        __shared__ float2 sh[32];
        float sx = 0.f, sy = 0.f;
        for (int j = threadIdx.x; j < n; j += blockDim.x) {
            float2 v = p[j];
            sx += v.x; sy += v.y;
        }
        sx = wsum(sx); sy = wsum(sy);
        int lane = threadIdx.x & 31, w = threadIdx.x >> 5;
        if (lane == 0) sh[w] = make_float2(sx, sy);
        __syncthreads();
        if (w == 0) {
            int nw = blockDim.x >> 5;
            float2 v = (lane < nw) ? sh[lane] : make_float2(0.f, 0.f);
            float ax = wsum(v.x), ay = wsum(v.y);
            if (lane == 0) {
                float inv = 1.0f / fmaxf((float)n, 1.0f);   // max(n_a,1), n_a = n
                g_cms = make_float2(ax * inv, ay * inv);
            }
        }
    }
}

// ---------------- main pairwise pass: 2 warps per particle, 8-wide MLP ------------
// Block = 128 threads = 4 warps = 2 particles x 2 j-halves. Grid = n/2.
__global__ void main_kernel(
        const float* __restrict__ deltas, const float* __restrict__ rnoise,
        const float* __restrict__ tnoise_, float* __restrict__ out, int n) {
    const float2* tn = (const float2*)tnoise_;
    __shared__ float red[4][5];

    const int w    = threadIdx.x >> 5;           // 0..3
    const int lane = threadIdx.x & 31;
    const int i    = blockIdx.x * 2 + (w >> 1);  // particle
    const int h    = w & 1;                      // j-half

    const float4 me = g_pu[i];
    const float pix = me.x, piy = me.y;

    const float RR2  = (float)(8e-6 * 8e-6);
    const float ROCf = (float)(2.5e-5 + 3.15e-6);
    const float ROC2 = ROCf * ROCf;
    const unsigned uRR2 = __float_as_uint(RR2);

    float nr = 0.f, srx = 0.f, sry = 0.f, osx = 0.f, osy = 0.f;

    // Half-range = n/2 (2048) j's; 8 independent float4 loads per lane per iter.
    const int start = h * (n >> 1);
    for (int base = start; base < start + (n >> 1); base += 256) {
        float4 a0 = g_pu[base + lane];
        float4 a1 = g_pu[base + lane + 32];
        float4 a2 = g_pu[base + lane + 64];
        float4 a3 = g_pu[base + lane + 96];
        float4 a4 = g_pu[base + lane + 128];
        float4 a5 = g_pu[base + lane + 160];
        float4 a6 = g_pu[base + lane + 192];
        float4 a7 = g_pu[base + lane + 224];
#pragma unroll
        for (int k = 0; k < 8; k++) {
            float4 a = (k == 0) ? a0 : (k == 1) ? a1 : (k == 2) ? a2 : (k == 3) ? a3
                     : (k == 4) ? a4 : (k == 5) ? a5 : (k == 6) ? a6 : a7;
            float dx = a.x - pix, dy = a.y - piy;
            float d2 = fmaf(dx, dx, dy * dy);
            if (d2 <= ROC2) {                         // rare; includes j==i
                osx += a.z; osy += a.w;               // mask_ro
                // inside_Rr excl. self: 0 < d2 <= RR2  <=>  bits(d2)-1 <u bits(RR2)
                if ((__float_as_uint(d2) - 1u) < uRR2) {
                    // in_front: wrap(angle(dir)-angle(u_j)) < pi/2
                    //   <=> !(dot<=0 && cross>=0)
                    float c = dx * a.z + dy * a.w;
                    float s = a.z * dy - a.w * dx;
                    if (!(c <= 0.0f && s >= 0.0f)) { nr += 1.f; srx += a.x; sry += a.y; }
                }
            }
        }
    }
    nr = wsum(nr); srx = wsum(srx); sry = wsum(sry); osx = wsum(osx); osy = wsum(osy);
    if (lane == 0) {
        red[w][0] = nr; red[w][1] = srx; red[w][2] = sry; red[w][3] = osx; red[w][4] = osy;
    }
    __syncthreads();

    // ---- per-particle epilogue: thread 0 & 1 each finish one particle ----
    if (threadIdx.x < 2) {
        const int ii = blockIdx.x * 2 + threadIdx.x;
        const int w0 = threadIdx.x * 2;
        float nrT  = red[w0][0] + red[w0 + 1][0];
        float srxT = red[w0][1] + red[w0 + 1][1];
        float sryT = red[w0][2] + red[w0 + 1][2];
        float osxT = red[w0][3] + red[w0 + 1][3];
        float osyT = red[w0][4] + red[w0 + 1][4];

        const float4 m = g_pu[ii];
        const float px = m.x, py = m.y, ux = m.z, uy = m.w;

        float sgn = (nrT > 0.f) ? 1.0f : 0.0f;
        float invr = 1.0f / fmaxf(nrT, 1.0f);
        float dax = -(srxT * invr - px * sgn);
        float day = -(sryT * invr - py * sgn);

        float2 cms = g_cms;
        float Psx = cms.x - px;                       // sign(n_a) == 1
        float Psy = cms.y - py;

        float Delta = __ldg(&deltas[0]);
        float cd = cosf(Delta), sd = sinf(Delta);
        float lx = Psx * cd - Psy * sd, ly = Psx * sd + Psy * cd;   // Ps*e^{+iD}
        float rx = Psx * cd + Psy * sd, ry = Psy * cd - Psx * sd;   // Ps*e^{-iD}

        const float EPSF = 1e-14f;
        float nb  = fmaxf(sqrtf(osxT * osxT + osyT * osyT + 1e-30f), EPSF);
        float naL = fmaxf(sqrtf(lx * lx + ly * ly + 1e-30f), EPSF);
        float naR = fmaxf(sqrtf(rx * rx + ry * ry + 1e-30f), EPSF);
        float csL = (lx * osxT + ly * osyT) / (naL * nb);
        float csR = (rx * osxT + ry * osyT) / (naR * nb);
        bool left_closer = (csL >= csR);
        float bx = left_closer ? lx : rx;
        float by = left_closer ? ly : ry;

        float d_abs = sqrtf(dax * dax + day * day);
        float ang;
        if (d_abs > 0.f) {
            ang = anglediff(dax, day, ux, uy);
        } else {
            float babs = sqrtf(bx * bx + by * by);
            float bsx = (babs > 0.f) ? bx : 1.0f;
            float bsy = (babs > 0.f) ? by : 0.0f;
            ang = anglediff(bsx, bsy, ux, uy);
        }

        const float C1   = (float)(0.2 * 25.0 * 0.0028);    // dt*Gamma*DR
        const float S2DR = (float)0.07483314773547883;      // sqrt(2*DR)
        const float SDT  = (float)0.4472135954999579;       // sqrt(dt)
        float phi = C1 * sinf(ang) + rnoise[ii] * S2DR * SDT;
        float cr = cosf(phi), sr = sinf(phi);
        float nux = ux * cr - uy * sr;
        float nuy = ux * sr + uy * cr;

        const float DTV = (float)(0.2 * 5e-7);
        const float CSH = (float)0.7071067811865476;        // sqrt(0.5)
        const float C2T = (float)1.6733200530681511e-07;    // sqrt(2*DT_trans)
        float2 t = __ldg(&tn[ii]);
        float tx = DTV * ux + ((t.x * CSH) * C2T) * SDT;
        float ty = DTV * uy + ((t.y * CSH) * C2T) * SDT;

        ((float2*)g_posA4)[ii] = make_float2(px + tx, py + ty);
        int b = 2 * n;
        out[1 * b + 2 * ii + 0] = nux;  out[1 * b + 2 * ii + 1] = nuy;
        out[2 * b + 2 * ii + 0] = osxT; out[2 * b + 2 * ii + 1] = osyT;
        out[3 * b + 2 * ii + 0] = lx;   out[3 * b + 2 * ii + 1] = ly;
        out[4 * b + 2 * ii + 0] = rx;   out[4 * b + 2 * ii + 1] = ry;
    }
}

// ---------------- collision sweep: 2 warps per particle, 8-wide MLP ---------------
// Block = 128 threads = 4 warps = 2 particles x 2 j-halves. Grid = n/2.
// pass 0: A->B, 1: B->A, 2: A->out_final.
__global__ void collide_kernel(int pass, float2* __restrict__ out_final, int n) {
    const float4* __restrict__ src4 = (pass == 1) ? g_posB4 : g_posA4;
    float2* dst = (pass == 0) ? (float2*)g_posB4 : (pass == 1) ? (float2*)g_posA4 : out_final;
    __shared__ float2 red[4];

    const int w    = threadIdx.x >> 5;
    const int lane = threadIdx.x & 31;
    const int i    = blockIdx.x * 2 + (w >> 1);
    const int h    = w & 1;

    const float2 pi = ((const float2*)src4)[i];
    const float TH2 = (float)(2.0 * 3.15e-6) * (float)(2.0 * 3.15e-6);
    const float C21 = (float)(2.1 * 3.15e-6);
    const unsigned uTH2 = __float_as_uint(TH2);

    float mvx = 0.f, mvy = 0.f;
    // Half-range = n/4 float4s (1024); 8 loads (16 j) per lane per iteration.
    const int start = h * (n >> 2);
    for (int fb = start; fb < start + (n >> 2); fb += 256) {
        float4 q0 = src4[fb + lane];
        float4 q1 = src4[fb + lane + 32];
        float4 q2 = src4[fb + lane + 64];
        float4 q3 = src4[fb + lane + 96];
        float4 q4 = src4[fb + lane + 128];
        float4 q5 = src4[fb + lane + 160];
        float4 q6 = src4[fb + lane + 192];
        float4 q7 = src4[fb + lane + 224];
#pragma unroll
        for (int k = 0; k < 8; k++) {
            float4 v = (k == 0) ? q0 : (k == 1) ? q1 : (k == 2) ? q2 : (k == 3) ? q3
                     : (k == 4) ? q4 : (k == 5) ? q5 : (k == 6) ? q6 : q7;
            float dxa = v.x - pi.x, dya = v.y - pi.y;
            float dxb = v.z - pi.x, dyb = v.w - pi.y;
            float d2a = fmaf(dxa, dxa, dya * dya);
            float d2b = fmaf(dxb, dxb, dyb * dyb);
            // hit iff 0 < d2 <= TH2 (d2==0 <=> self)
            bool hitA = (__float_as_uint(d2a) - 1u) < uTH2;
            bool hitB = (__float_as_uint(d2b) - 1u) < uTH2;
            if (hitA || hitB) {                         // rare
                if (hitA) {
                    float ab = sqrtf(d2a);
                    float sc = (C21 - ab) * 0.5f / ab;
                    mvx += dxa * sc; mvy += dya * sc;
                }
                if (hitB) {
                    float ab = sqrtf(d2b);
                    float sc = (C21 - ab) * 0.5f / ab;
                    mvx += dxb * sc; mvy += dyb * sc;
                }
            }
        }
    }
    mvx = wsum(mvx); mvy = wsum(mvy);
    if (lane == 0) red[w] = make_float2(mvx, mvy);
    __syncthreads();
    if (threadIdx.x < 2) {
        const int ii = blockIdx.x * 2 + threadIdx.x;
        float2 r0 = red[threadIdx.x * 2], r1 = red[threadIdx.x * 2 + 1];
        float2 pv = ((const float2*)src4)[ii];
        dst[ii] = make_float2(pv.x - (r0.x + r1.x), pv.y - (r0.y + r1.y));
    }
}

extern "C" void kernel_launch(void* const* d_in, const int* in_sizes, int n_in,
                              void* d_out, int out_size) {
    const float* pos = (const float*)d_in[0];
    const float* ori = (const float*)d_in[1];
    const float* del = (const float*)d_in[2];
    const float* rno = (const float*)d_in[3];
    const float* tno = (const float*)d_in[4];
    float* out = (float*)d_out;
    const int n = in_sizes[3];                  // rot_noise has N elements

    const int blocks = n / 2;                   // 2 particles per 128-thread block

    prep_kernel<<<(n + 1023) / 1024, 1024>>>((const float2*)pos, (const float2*)ori, n);
    main_kernel<<<blocks, 128>>>(del, rno, tno, out, n);
    collide_kernel<<<blocks, 128>>>(0, nullptr, n);
    collide_kernel<<<blocks, 128>>>(1, nullptr, n);
    collide_kernel<<<blocks, 128>>>(2, (float2*)out, n);
}

// round 7
// speedup vs baseline: 1.0593x; 1.0593x over previous
#include <cuda_runtime.h>

// ActiveParticles step, N=4096 — single fused persistent kernel.
// Inputs: positions[N,2] f32, orientations[N,2] f32, Deltas[1] f32,
//         rot_noise[N] f32, trans_noise[N,2] f32.
// Output: [5, N, 2] f32 = {new_p, new_u, orientation_sums, leftturns, rightturns}.

#define NMAX 4096

static __device__ float4 g_pu[NMAX];             // (p.x, p.y, u.x, u.y)
static __device__ float2 g_part[NMAX / 128];     // per-block partial sums for mean
static __device__ float4 g_posA4[NMAX / 2];      // positions ping (float2 pairs)
static __device__ float4 g_posB4[NMAX / 2];      // positions pong
static __device__ volatile unsigned g_gen;       // barrier generation
static __device__ unsigned g_count;              // barrier arrival count

__device__ __forceinline__ float wsum(float v) {
#pragma unroll
    for (int o = 16; o; o >>= 1) v += __shfl_xor_sync(0xffffffffu, v, o);
    return v;
}

__device__ __forceinline__ float anglewrap(float diff) {
    const float PI_F = 3.1415927410125732f;
    if (diff <= -PI_F) diff = diff - PI_F * floorf(diff / PI_F);  // jnp.mod(diff, PI)
    if (diff >= PI_F) diff -= 2.0f * PI_F;
    return diff;
}

__device__ __forceinline__ float anglediff(float ax, float ay, float bx, float by) {
    return anglewrap(atan2f(ay, ax) - atan2f(by, bx));
}

// Software grid barrier. All nb blocks must be co-resident (guaranteed by
// launch_bounds(128,9): capacity 9*148=1332 >= 1024). The trailing
// __threadfence() is gpu-scope -> CCTL.IVALL: invalidates this SM's L1D so
// post-barrier loads of other SMs' writes refetch from (coherent) L2.
__device__ __forceinline__ void grid_sync(unsigned nb) {
    __syncthreads();
    if (threadIdx.x == 0) {
        unsigned my = g_gen;                       // read BEFORE arriving
        __threadfence();                           // release our writes
        if (atomicAdd(&g_count, 1u) == nb - 1u) {
            g_count = 0u;
            __threadfence();
            g_gen = my + 1u;                       // release the barrier
        } else {
            while (g_gen == my) __nanosleep(40);
        }
        __threadfence();                           // acquire + L1D invalidate
    }
    __syncthreads();
}

// One collision sweep for particle i (one warp), 8-wide MLP. R5-proven body.
__device__ __forceinline__ void collide_phase(const float4* __restrict__ src4,
                                              float2* __restrict__ dst,
                                              int n, int i, int lane) {
    const float2 pi = ((const float2*)src4)[i];
    const float TH2 = (float)(2.0 * 3.15e-6) * (float)(2.0 * 3.15e-6);
    const float C21 = (float)(2.1 * 3.15e-6);
    const unsigned uTH2 = __float_as_uint(TH2);

    float mvx = 0.f, mvy = 0.f;
    for (int fb = 0; fb < (n >> 1); fb += 256) {
        float4 q0 = src4[fb + lane];
        float4 q1 = src4[fb + lane + 32];
        float4 q2 = src4[fb + lane + 64];
        float4 q3 = src4[fb + lane + 96];
        float4 q4 = src4[fb + lane + 128];
        float4 q5 = src4[fb + lane + 160];
        float4 q6 = src4[fb + lane + 192];
        float4 q7 = src4[fb + lane + 224];
#pragma unroll
        for (int k = 0; k < 8; k++) {
            float4 v = (k == 0) ? q0 : (k == 1) ? q1 : (k == 2) ? q2 : (k == 3) ? q3
                     : (k == 4) ? q4 : (k == 5) ? q5 : (k == 6) ? q6 : q7;
            float dxa = v.x - pi.x, dya = v.y - pi.y;
            float dxb = v.z - pi.x, dyb = v.w - pi.y;
            float d2a = fmaf(dxa, dxa, dya * dya);
            float d2b = fmaf(dxb, dxb, dyb * dyb);
            // hit iff 0 < d2 <= TH2 (d2==0 <=> self)
            bool hitA = (__float_as_uint(d2a) - 1u) < uTH2;
            bool hitB = (__float_as_uint(d2b) - 1u) < uTH2;
            if (hitA || hitB) {                          // rare
                if (hitA) {
                    float ab = sqrtf(d2a);
                    float sc = (C21 - ab) * 0.5f / ab;
                    mvx += dxa * sc; mvy += dya * sc;
                }
                if (hitB) {
                    float ab = sqrtf(d2b);
                    float sc = (C21 - ab) * 0.5f / ab;
                    mvx += dxb * sc; mvy += dyb * sc;
                }
            }
        }
    }
    mvx = wsum(mvx); mvy = wsum(mvy);
    if (lane == 0) dst[i] = make_float2(pi.x - mvx, pi.y - mvy);
}

__global__ void __launch_bounds__(128, 9) fused_kernel(
        const float2* __restrict__ pos, const float2* __restrict__ ori,
        const float* __restrict__ deltas, const float* __restrict__ rnoise,
        const float2* __restrict__ tn, float* __restrict__ out,
        int n, unsigned nb) {
    const int tid  = threadIdx.x;
    const int bid  = blockIdx.x;
    const int w    = tid >> 5;
    const int lane = tid & 31;
    __shared__ float2 shm[4];

    // ---------------- phase 0: pack (p,u); per-block partial sums of p ------------
    const int pblocks = n >> 7;                   // 128 particles per pack block
    if (bid < pblocks) {
        int i = bid * 128 + tid;
        float2 pp = pos[i], uu = ori[i];
        g_pu[i] = make_float4(pp.x, pp.y, uu.x, uu.y);
        float sx = wsum(pp.x), sy = wsum(pp.y);
        if (lane == 0) shm[w] = make_float2(sx, sy);
        __syncthreads();
        if (tid == 0)
            g_part[bid] = make_float2(shm[0].x + shm[1].x + shm[2].x + shm[3].x,
                                      shm[0].y + shm[1].y + shm[2].y + shm[3].y);
    }
    grid_sync(nb);

    // ---------------- phase 1: main pairwise pass, one warp per particle ----------
    {
        const int i = bid * 4 + w;
        const float4 me = g_pu[i];
        const float pix = me.x, piy = me.y, uix = me.z, uiy = me.w;

        const float RR2  = (float)(8e-6 * 8e-6);
        const float ROCf = (float)(2.5e-5 + 3.15e-6);
        const float ROC2 = ROCf * ROCf;
        const unsigned uRR2 = __float_as_uint(RR2);

        float nr = 0.f, srx = 0.f, sry = 0.f, osx = 0.f, osy = 0.f;

        for (int base = 0; base < n; base += 256) {
            float4 a0 = g_pu[base + lane];
            float4 a1 = g_pu[base + lane + 32];
            float4 a2 = g_pu[base + lane + 64];
            float4 a3 = g_pu[base + lane + 96];
            float4 a4 = g_pu[base + lane + 128];
            float4 a5 = g_pu[base + lane + 160];
            float4 a6 = g_pu[base + lane + 192];
            float4 a7 = g_pu[base + lane + 224];
#pragma unroll
            for (int k = 0; k < 8; k++) {
                float4 a = (k == 0) ? a0 : (k == 1) ? a1 : (k == 2) ? a2 : (k == 3) ? a3
                         : (k == 4) ? a4 : (k == 5) ? a5 : (k == 6) ? a6 : a7;
                float dx = a.x - pix, dy = a.y - piy;
                float d2 = fmaf(dx, dx, dy * dy);
                if (d2 <= ROC2) {                     // rare; includes j==i
                    osx += a.z; osy += a.w;           // mask_ro
                    // inside_Rr excl. self: 0 < d2 <= RR2
                    if ((__float_as_uint(d2) - 1u) < uRR2) {
                        // in_front: wrap(angle(dir)-angle(u_j)) < pi/2
                        //   <=> !(dot<=0 && cross>=0)
                        float c = dx * a.z + dy * a.w;
                        float s = a.z * dy - a.w * dx;
                        if (!(c <= 0.0f && s >= 0.0f)) { nr += 1.f; srx += a.x; sry += a.y; }
                    }
                }
            }
        }
        nr = wsum(nr); srx = wsum(srx); sry = wsum(sry); osx = wsum(osx); osy = wsum(osy);

        // ---- epilogue (all lanes redundant, lane 0 writes) ----
        float cx = 0.f, cy = 0.f;
#pragma unroll 4
        for (int k2 = 0; k2 < pblocks; k2++) { float2 v = g_part[k2]; cx += v.x; cy += v.y; }
        float invn = 1.0f / fmaxf((float)n, 1.0f);    // max(n_a,1), n_a = n
        float cmx = cx * invn, cmy = cy * invn;

        float sgn = (nr > 0.f) ? 1.0f : 0.0f;
        float invr = 1.0f / fmaxf(nr, 1.0f);
        float dax = -(srx * invr - pix * sgn);
        float day = -(sry * invr - piy * sgn);

        float Psx = cmx - pix;                        // sign(n_a) == 1
        float Psy = cmy - piy;

        float Delta = __ldg(&deltas[0]);
        float cd = cosf(Delta), sd = sinf(Delta);
        float lx = Psx * cd - Psy * sd, ly = Psx * sd + Psy * cd;  // Ps*e^{+iD}
        float rx = Psx * cd + Psy * sd, ry = Psy * cd - Psx * sd;  // Ps*e^{-iD}

        const float EPSF = 1e-14f;
        float nbn = fmaxf(sqrtf(osx * osx + osy * osy + 1e-30f), EPSF);
        float naL = fmaxf(sqrtf(lx * lx + ly * ly + 1e-30f), EPSF);
        float naR = fmaxf(sqrtf(rx * rx + ry * ry + 1e-30f), EPSF);
        float csL = (lx * osx + ly * osy) / (naL * nbn);
        float csR = (rx * osx + ry * osy) / (naR * nbn);
        bool left_closer = (csL >= csR);
        float bx = left_closer ? lx : rx;
        float by = left_closer ? ly : ry;

        float d_abs = sqrtf(dax * dax + day * day);
        float ang;
        if (d_abs > 0.f) {
            ang = anglediff(dax, day, uix, uiy);
        } else {
            float babs = sqrtf(bx * bx + by * by);
            float bsx = (babs > 0.f) ? bx : 1.0f;
            float bsy = (babs > 0.f) ? by : 0.0f;
            ang = anglediff(bsx, bsy, uix, uiy);
        }

        const float C1   = (float)(0.2 * 25.0 * 0.0028);   // dt*Gamma*DR
        const float S2DR = (float)0.07483314773547883;     // sqrt(2*DR)
        const float SDT  = (float)0.4472135954999579;      // sqrt(dt)
        float phi = C1 * sinf(ang) + rnoise[i] * S2DR * SDT;
        float cr = cosf(phi), sr = sinf(phi);
        float nux = uix * cr - uiy * sr;
        float nuy = uix * sr + uiy * cr;

        const float DTV = (float)(0.2 * 5e-7);
        const float CSH = (float)0.7071067811865476;       // sqrt(0.5)
        const float C2T = (float)1.6733200530681511e-07;   // sqrt(2*DT_trans)
        float2 t = __ldg(&tn[i]);
        float tx = DTV * uix + ((t.x * CSH) * C2T) * SDT;
        float ty = DTV * uiy + ((t.y * CSH) * C2T) * SDT;

        if (lane == 0) {
            ((float2*)g_posA4)[i] = make_float2(pix + tx, piy + ty);
            int b = 2 * n;
            out[1 * b + 2 * i + 0] = nux;  out[1 * b + 2 * i + 1] = nuy;
            out[2 * b + 2 * i + 0] = osx;  out[2 * b + 2 * i + 1] = osy;
            out[3 * b + 2 * i + 0] = lx;   out[3 * b + 2 * i + 1] = ly;
            out[4 * b + 2 * i + 0] = rx;   out[4 * b + 2 * i + 1] = ry;
        }
    }
    grid_sync(nb);

    // ---------------- phases 2-4: three collision sweeps --------------------------
    collide_phase(g_posA4, (float2*)g_posB4, n, bid * 4 + w, lane);
    grid_sync(nb);
    collide_phase(g_posB4, (float2*)g_posA4, n, bid * 4 + w, lane);
    grid_sync(nb);
    collide_phase(g_posA4, (float2*)out, n, bid * 4 + w, lane);  // new_p block
}

extern "C" void kernel_launch(void* const* d_in, const int* in_sizes, int n_in,
                              void* d_out, int out_size) {
    const float* pos = (const float*)d_in[0];
    const float* ori = (const float*)d_in[1];
    const float* del = (const float*)d_in[2];
    const float* rno = (const float*)d_in[3];
    const float* tno = (const float*)d_in[4];
    float* out = (float*)d_out;
    const int n = in_sizes[3];                    // rot_noise has N elements

    const unsigned nb = (unsigned)(n / 4);        // 1024 blocks, all co-resident
    fused_kernel<<<nb, 128>>>((const float2*)pos, (const float2*)ori, del, rno,
                              (const float2*)tno, out, n, nb);
}